// round 5
// baseline (speedup 1.0000x reference)
#include <cuda_runtime.h>
#include <math.h>

#define BATCH 16
#define SEQ 1024
#define IN_DIM 310
#define E 64
#define NH 8
#define HD 8
#define ROWS (BATCH*SEQ)          // 16384
#define WIN 5
#define NKEYS 342                 // #{j < 1024 : j%3==0}
#define SCALE 0.35355339059327373f  // 1/sqrt(8)

typedef unsigned long long ull;

// ---------------- f32x2 packed helpers ----------------
__device__ __forceinline__ ull pk2(float lo, float hi) {
    ull r; asm("mov.b64 %0,{%1,%2};" : "=l"(r) : "f"(lo), "f"(hi)); return r;
}
__device__ __forceinline__ void upk2(ull v, float& lo, float& hi) {
    asm("mov.b64 {%0,%1},%2;" : "=f"(lo), "=f"(hi) : "l"(v));
}
__device__ __forceinline__ ull ffma2(ull a, ull b, ull c) {
    ull d; asm("fma.rn.f32x2 %0,%1,%2,%3;" : "=l"(d) : "l"(a), "l"(b), "l"(c)); return d;
}
__device__ __forceinline__ ull fmul2(ull a, ull b) {
    ull d; asm("mul.rn.f32x2 %0,%1,%2;" : "=l"(d) : "l"(a), "l"(b)); return d;
}

// ---------------- scratch (static device memory; no allocation) ----------------
__device__ float g_xp[ROWS*E];                 // projected input [row][64]
__device__ float g_q[2][BATCH*NH*SEQ*HD];      // [attn][b*NH+h][s][d]
__device__ float g_k[2][BATCH*NH*SEQ*HD];
__device__ float g_v[2][BATCH*NH*SEQ*HD];
__device__ float g_o[2][ROWS*E];               // attention out, head-concat layout
__device__ float g_M[2][E*E];                  // combined fusion matrices
__device__ float g_cb[E];                      // combined bias
__device__ float g_scores[ROWS];               // pooling logits
__device__ float g_fused[ROWS*E];              // fused features

// ---------------- GEMM tile: 64 rows x 64 cols, 256 threads, microtile 4x4 ----------------
struct GemmSmem {
    float As[16][68];
    float Ws[16][68];
};

__device__ __forceinline__ void gemm_tile64(
    GemmSmem& sm,
    const float* __restrict__ A, int lda, int row0,
    const float* __restrict__ W, int ldw,
    int Kdim, ull (&acc)[2][4], int tid)
{
    int tc = tid & 15, tr = tid >> 4;
    for (int k0 = 0; k0 < Kdim; k0 += 16) {
        #pragma unroll
        for (int p = 0; p < 4; p++) {
            int i = tid + p * 256;
            int kk = i & 15, r = i >> 4;
            int k = k0 + kk;
            sm.As[kk][r] = (k < Kdim) ? A[(size_t)(row0 + r) * lda + k] : 0.f;
        }
        #pragma unroll
        for (int p = 0; p < 4; p++) {
            int i = tid + p * 256;
            int kk = i & 15, c = i >> 4;
            int k = k0 + kk;
            sm.Ws[kk][c] = (k < Kdim) ? W[(size_t)c * ldw + k] : 0.f;
        }
        __syncthreads();
        #pragma unroll
        for (int kk = 0; kk < 16; kk++) {
            ulonglong2 a01 = *(const ulonglong2*)&sm.As[kk][4*tr];
            float4 wv = *(const float4*)&sm.Ws[kk][4*tc];
            ull w2[4] = {pk2(wv.x, wv.x), pk2(wv.y, wv.y), pk2(wv.z, wv.z), pk2(wv.w, wv.w)};
            #pragma unroll
            for (int j = 0; j < 4; j++) {
                acc[0][j] = ffma2(a01.x, w2[j], acc[0][j]);
                acc[1][j] = ffma2(a01.y, w2[j], acc[1][j]);
            }
        }
        __syncthreads();
    }
}

// ---------------- combine_w (blocks 0..15) + proj (blocks 16..271) ----------------
__global__ __launch_bounds__(256) void combine_proj_kernel(
    const float* __restrict__ x,
    const float* __restrict__ pw, const float* __restrict__ pb,
    const float* __restrict__ fw, const float* __restrict__ fb,
    const float* __restrict__ low, const float* __restrict__ lob,
    const float* __restrict__ gow, const float* __restrict__ gob)
{
    __shared__ GemmSmem sm;
    int tid = threadIdx.x;
    int blk = blockIdx.x;
    if (blk < 16) {
        int idx = blk * 256 + tid;             // 0..4095
        int e = idx >> 6, f = idx & 63;
        float a = 0.f, b = 0.f;
        #pragma unroll 4
        for (int g = 0; g < E; g++) {
            a = fmaf(fw[e*2*E + g],     low[g*E + f], a);
            b = fmaf(fw[e*2*E + E + g], gow[g*E + f], b);
        }
        g_M[0][idx] = a;
        g_M[1][idx] = b;
        if (idx < E) {
            float c = fb[idx];
            for (int g = 0; g < E; g++) {
                c = fmaf(fw[idx*2*E + g], lob[g], c);
                c = fmaf(fw[idx*2*E + E + g], gob[g], c);
            }
            g_cb[idx] = c;
        }
        return;
    }
    int row0 = (blk - 16) * 64;
    ull acc[2][4] = {};
    gemm_tile64(sm, x, IN_DIM, row0, pw, IN_DIM, IN_DIM, acc, tid);
    int tc = tid & 15, tr = tid >> 4;
    float4 bias = *(const float4*)&pb[4*tc];
    #pragma unroll
    for (int p = 0; p < 2; p++) {
        float lo[4], hi[4];
        #pragma unroll
        for (int j = 0; j < 4; j++) upk2(acc[p][j], lo[j], hi[j]);
        int row = row0 + 4*tr + 2*p;
        float4 v0 = {lo[0]+bias.x, lo[1]+bias.y, lo[2]+bias.z, lo[3]+bias.w};
        float4 v1 = {hi[0]+bias.x, hi[1]+bias.y, hi[2]+bias.z, hi[3]+bias.w};
        *(float4*)&g_xp[(size_t)row*E + 4*tc] = v0;
        *(float4*)&g_xp[(size_t)(row+1)*E + 4*tc] = v1;
    }
}

// ---------------- QKV: one block = 64 rows x all 192 cols (q,k,v) ----------------
__global__ __launch_bounds__(256) void qkv_kernel(const float* __restrict__ loc_w,
                           const float* __restrict__ loc_b,
                           const float* __restrict__ glb_w,
                           const float* __restrict__ glb_b) {
    __shared__ float As[16][68];
    __shared__ float Ws[16][196];
    int tid = threadIdx.x;
    int row0 = blockIdx.x * 64;
    int attn = blockIdx.y;
    const float* w    = attn ? glb_w : loc_w;
    const float* bias = attn ? glb_b : loc_b;
    int tc = tid & 15, tr = tid >> 4;
    ull acc[2][12] = {};
    for (int k0 = 0; k0 < E; k0 += 16) {
        #pragma unroll
        for (int p = 0; p < 4; p++) {          // A: 64x16
            int i = tid + p * 256;
            int kk = i & 15, r = i >> 4;
            As[kk][r] = g_xp[(size_t)(row0 + r) * E + k0 + kk];
        }
        #pragma unroll
        for (int p = 0; p < 12; p++) {         // W: 192x16
            int i = tid + p * 256;
            int kk = i & 15, c = i >> 4;
            Ws[kk][c] = w[(size_t)c * E + k0 + kk];
        }
        __syncthreads();
        #pragma unroll
        for (int kk = 0; kk < 16; kk++) {
            ulonglong2 a01 = *(const ulonglong2*)&As[kk][4*tr];
            #pragma unroll
            for (int cg = 0; cg < 3; cg++) {
                float4 wv = *(const float4*)&Ws[kk][64*cg + 4*tc];
                ull w2[4] = {pk2(wv.x, wv.x), pk2(wv.y, wv.y), pk2(wv.z, wv.z), pk2(wv.w, wv.w)};
                #pragma unroll
                for (int j = 0; j < 4; j++) {
                    acc[0][cg*4+j] = ffma2(a01.x, w2[j], acc[0][cg*4+j]);
                    acc[1][cg*4+j] = ffma2(a01.y, w2[j], acc[1][cg*4+j]);
                }
            }
        }
        __syncthreads();
    }
    int c = 4*tc;
    int h = c >> 3, dd = c & 7;
    #pragma unroll
    for (int cg = 0; cg < 3; cg++) {
        float* outp = (cg == 0) ? g_q[attn] : (cg == 1) ? g_k[attn] : g_v[attn];
        float4 bv = *(const float4*)&bias[cg*64 + c];
        #pragma unroll
        for (int p = 0; p < 2; p++) {
            float lo[4], hi[4];
            #pragma unroll
            for (int j = 0; j < 4; j++) upk2(acc[p][cg*4+j], lo[j], hi[j]);
            int row = row0 + 4*tr + 2*p;
            int b0 = row >> 10, s0 = row & 1023;
            int b1 = (row+1) >> 10, s1 = (row+1) & 1023;
            float4 v0 = {lo[0]+bv.x, lo[1]+bv.y, lo[2]+bv.z, lo[3]+bv.w};
            float4 v1 = {hi[0]+bv.x, hi[1]+bv.y, hi[2]+bv.z, hi[3]+bv.w};
            *(float4*)&outp[(((size_t)(b0*NH + h))*SEQ + s0)*HD + dd] = v0;
            *(float4*)&outp[(((size_t)(b1*NH + h))*SEQ + s1)*HD + dd] = v1;
        }
    }
}

// ---------------- both attentions in one launch ----------------
__global__ __launch_bounds__(256) void attn_kernel() {
    __shared__ union {
        struct { float Ks[NKEYS][8]; float Vs[NKEYS][8]; } sp;   // 21.9 KB
        struct { ull K2[4][272]; ull V2[4][272]; } loc;           // 17.4 KB
    } u;
    int blk = blockIdx.x;
    int tid = threadIdx.x;
    if (blk < 512) {
        // ---- local path ----
        int bh = blk >> 2;
        int chunk0 = (blk & 3) * 256;
        const float* kb = g_k[0] + (size_t)bh * SEQ * HD;
        const float* vb = g_v[0] + (size_t)bh * SEQ * HD;
        for (int i = tid; i < 266*4; i += 256) {
            int dp = i & 3, r = i >> 2;
            int row = chunk0 - 5 + r;
            ull kv = 0, vv = 0;
            if (row >= 0 && row < SEQ) {
                kv = *(const ull*)(kb + (size_t)row*HD + 2*dp);
                vv = *(const ull*)(vb + (size_t)row*HD + 2*dp);
            }
            u.loc.K2[dp][r] = kv;
            u.loc.V2[dp][r] = vv;
        }
        __syncthreads();
        int s = chunk0 + tid;
        const ull* qp = (const ull*)(g_q[0] + ((size_t)bh * SEQ + s) * HD);
        ull q0 = qp[0], q1 = qp[1], q2 = qp[2], q3 = qp[3];
        float l = 0.f;
        ull acc[4] = {0,0,0,0};
        int j0 = s - WIN;
        #pragma unroll
        for (int jj = 0; jj < 2*WIN+1; jj++) {
            int r = tid + jj;
            ull d2 = ffma2(q0, u.loc.K2[0][r],
                     ffma2(q1, u.loc.K2[1][r],
                     ffma2(q2, u.loc.K2[2][r],
                     fmul2(q3, u.loc.K2[3][r]))));
            float dl, dh; upk2(d2, dl, dh);
            unsigned jg = (unsigned)(j0 + jj);
            float p = (jg < SEQ) ? __expf((dl + dh) * SCALE) : 0.f;
            l += p;
            ull pp = pk2(p, p);
            acc[0] = ffma2(pp, u.loc.V2[0][r], acc[0]);
            acc[1] = ffma2(pp, u.loc.V2[1][r], acc[1]);
            acc[2] = ffma2(pp, u.loc.V2[2][r], acc[2]);
            acc[3] = ffma2(pp, u.loc.V2[3][r], acc[3]);
        }
        float inv = 1.f / l;
        float oo[8];
        upk2(acc[0], oo[0], oo[1]); upk2(acc[1], oo[2], oo[3]);
        upk2(acc[2], oo[4], oo[5]); upk2(acc[3], oo[6], oo[7]);
        int b = bh >> 3, h = bh & 7;
        float* op = g_o[0] + ((size_t)(b*SEQ + s))*E + h*HD;
        float4 o0 = {oo[0]*inv, oo[1]*inv, oo[2]*inv, oo[3]*inv};
        float4 o1 = {oo[4]*inv, oo[5]*inv, oo[6]*inv, oo[7]*inv};
        *(float4*)op = o0;
        *(float4*)(op + 4) = o1;
    } else {
        // ---- sparse path ----
        int bb = blk - 512;
        int bh = bb >> 2;
        int s  = (bb & 3) * 256 + tid;
        const float* kb = g_k[1] + (size_t)bh * SEQ * HD;
        const float* vb = g_v[1] + (size_t)bh * SEQ * HD;
        for (int i = tid; i < NKEYS*8; i += 256) {
            int kk = i >> 3, dd = i & 7;
            u.sp.Ks[kk][dd] = kb[kk*24 + dd];     // key row 3*kk
            u.sp.Vs[kk][dd] = vb[kk*24 + dd];
        }
        __syncthreads();
        const ull* qp = (const ull*)(g_q[1] + ((size_t)bh * SEQ + s) * HD);
        ull q0 = qp[0], q1 = qp[1], q2 = qp[2], q3 = qp[3];
        float l = 0.f;
        ull acc[4] = {0,0,0,0};
        #pragma unroll 2
        for (int kk = 0; kk < NKEYS; kk++) {
            const ull* kp = (const ull*)&u.sp.Ks[kk][0];
            ull d2 = ffma2(q0, kp[0], ffma2(q1, kp[1], ffma2(q2, kp[2], fmul2(q3, kp[3]))));
            float dl, dh; upk2(d2, dl, dh);
            float p = __expf((dl + dh) * SCALE);
            l += p;
            ull pp = pk2(p, p);
            const ull* vp = (const ull*)&u.sp.Vs[kk][0];
            acc[0] = ffma2(pp, vp[0], acc[0]);
            acc[1] = ffma2(pp, vp[1], acc[1]);
            acc[2] = ffma2(pp, vp[2], acc[2]);
            acc[3] = ffma2(pp, vp[3], acc[3]);
        }
        if (s % 3) {
            const ull* kp = (const ull*)(kb + (size_t)s * HD);
            ull d2 = ffma2(q0, kp[0], ffma2(q1, kp[1], ffma2(q2, kp[2], fmul2(q3, kp[3]))));
            float dl, dh; upk2(d2, dl, dh);
            float p = __expf((dl + dh) * SCALE);
            l += p;
            ull pp = pk2(p, p);
            const ull* vp = (const ull*)(vb + (size_t)s * HD);
            acc[0] = ffma2(pp, vp[0], acc[0]);
            acc[1] = ffma2(pp, vp[1], acc[1]);
            acc[2] = ffma2(pp, vp[2], acc[2]);
            acc[3] = ffma2(pp, vp[3], acc[3]);
        }
        float inv = 1.f / l;
        float oo[8];
        upk2(acc[0], oo[0], oo[1]); upk2(acc[1], oo[2], oo[3]);
        upk2(acc[2], oo[4], oo[5]); upk2(acc[3], oo[6], oo[7]);
        int b = bh >> 3, h = bh & 7;
        float* op = g_o[1] + ((size_t)(b*SEQ + s))*E + h*HD;
        float4 o0 = {oo[0]*inv, oo[1]*inv, oo[2]*inv, oo[3]*inv};
        float4 o1 = {oo[4]*inv, oo[5]*inv, oo[6]*inv, oo[7]*inv};
        *(float4*)op = o0;
        *(float4*)(op + 4) = o1;
    }
}

// ---------------- fused GEMM + pooling scores in one kernel ----------------
__global__ __launch_bounds__(256) void fused_score_kernel(
    const float* __restrict__ w1, const float* __restrict__ b1,
    const float* __restrict__ w2, const float* __restrict__ b2)
{
    __shared__ GemmSmem sm;
    __shared__ float w1s[32][65];
    __shared__ float w2s[32], b1s[32];
    int tid = threadIdx.x;
    int row0 = blockIdx.x * 64;
    // stage pool weights (independent of GEMM smem)
    for (int i = tid; i < 32*64; i += 256)
        w1s[i >> 6][i & 63] = w1[i];
    if (tid < 32) { w2s[tid] = w2[tid]; b1s[tid] = b1[tid]; }
    ull acc[2][4] = {};
    gemm_tile64(sm, g_o[0], E, row0, g_M[0], E, E, acc, tid);
    gemm_tile64(sm, g_o[1], E, row0, g_M[1], E, E, acc, tid);
    int tc = tid & 15, tr = tid >> 4;
    float4 bias = *(const float4*)&g_cb[4*tc];
    #pragma unroll
    for (int p = 0; p < 2; p++) {
        float lo[4], hi[4];
        #pragma unroll
        for (int j = 0; j < 4; j++) upk2(acc[p][j], lo[j], hi[j]);
        int row = row0 + 4*tr + 2*p;
        float4 v0 = {lo[0]+bias.x, lo[1]+bias.y, lo[2]+bias.z, lo[3]+bias.w};
        float4 v1 = {hi[0]+bias.x, hi[1]+bias.y, hi[2]+bias.z, hi[3]+bias.w};
        *(float4*)&g_fused[(size_t)row*E + 4*tc] = v0;
        *(float4*)&g_fused[(size_t)(row+1)*E + 4*tc] = v1;
    }
    __syncthreads();   // g_fused rows of this block visible; w1s ready
    // scores for our 64 rows: 8 warps x 8 rows
    int warp = tid >> 5, lane = tid & 31;
    float b2v = b2[0];
    #pragma unroll
    for (int rr = 0; rr < 8; rr++) {
        int row = row0 + warp * 8 + rr;
        const float* fr = g_fused + (size_t)row * E;
        float f0 = fr[lane], f1 = fr[lane + 32];
        float h = 0.f;
        #pragma unroll
        for (int e = 0; e < 32; e++) {
            float v = __shfl_sync(0xffffffffu, f0, e);
            h = fmaf(v, w1s[lane][e], h);
        }
        #pragma unroll
        for (int e = 0; e < 32; e++) {
            float v = __shfl_sync(0xffffffffu, f1, e);
            h = fmaf(v, w1s[lane][e + 32], h);
        }
        h = tanhf(h + b1s[lane]);
        float p = h * w2s[lane];
        #pragma unroll
        for (int off = 16; off; off >>= 1)
            p += __shfl_xor_sync(0xffffffffu, p, off);
        if (lane == 0) g_scores[row] = p + b2v;
    }
}

// ---------------- softmax over seq + weighted sum -> out[b][e] ----------------
__global__ void pool_out_kernel(float* __restrict__ out) {
    int b = blockIdx.x;
    int tid = threadIdx.x;  // 256
    __shared__ float ws[SEQ];
    __shared__ float red[8];
    __shared__ float s_max, s_sum;
    __shared__ float part[4][64];
    const float* sc = g_scores + (size_t)b * SEQ;
    float m = -1e30f;
    for (int i = tid; i < SEQ; i += 256) m = fmaxf(m, sc[i]);
    #pragma unroll
    for (int off = 16; off; off >>= 1) m = fmaxf(m, __shfl_xor_sync(0xffffffffu, m, off));
    if ((tid & 31) == 0) red[tid >> 5] = m;
    __syncthreads();
    if (tid == 0) {
        float mm = red[0];
        for (int i = 1; i < 8; i++) mm = fmaxf(mm, red[i]);
        s_max = mm;
    }
    __syncthreads();
    float mm = s_max;
    float lsum = 0.f;
    for (int i = tid; i < SEQ; i += 256) {
        float e = __expf(sc[i] - mm);
        ws[i] = e;
        lsum += e;
    }
    #pragma unroll
    for (int off = 16; off; off >>= 1) lsum += __shfl_xor_sync(0xffffffffu, lsum, off);
    __syncthreads();
    if ((tid & 31) == 0) red[tid >> 5] = lsum;
    __syncthreads();
    if (tid == 0) {
        float ss = 0.f;
        for (int i = 0; i < 8; i++) ss += red[i];
        s_sum = ss;
    }
    __syncthreads();
    int e = tid & 63, g = tid >> 6;
    const float* fb = g_fused + (size_t)b * SEQ * E;
    float a = 0.f;
    for (int s = g*256; s < g*256 + 256; s++)
        a = fmaf(ws[s], fb[(size_t)s*E + e], a);
    part[g][e] = a;
    __syncthreads();
    if (tid < 64)
        out[b*64 + tid] = (part[0][tid] + part[1][tid] + part[2][tid] + part[3][tid]) / s_sum;
}

// ---------------- launch ----------------
extern "C" void kernel_launch(void* const* d_in, const int* in_sizes, int n_in,
                              void* d_out, int out_size) {
    const float* x        = (const float*)d_in[0];
    const float* proj_w   = (const float*)d_in[1];
    const float* proj_b   = (const float*)d_in[2];
    const float* loc_in_w = (const float*)d_in[3];
    const float* loc_in_b = (const float*)d_in[4];
    const float* loc_out_w= (const float*)d_in[5];
    const float* loc_out_b= (const float*)d_in[6];
    const float* glb_in_w = (const float*)d_in[7];
    const float* glb_in_b = (const float*)d_in[8];
    const float* glb_out_w= (const float*)d_in[9];
    const float* glb_out_b= (const float*)d_in[10];
    const float* fusion_w = (const float*)d_in[11];
    const float* fusion_b = (const float*)d_in[12];
    const float* pool_w1  = (const float*)d_in[13];
    const float* pool_b1  = (const float*)d_in[14];
    const float* pool_w2  = (const float*)d_in[15];
    const float* pool_b2  = (const float*)d_in[16];
    float* out = (float*)d_out;

    combine_proj_kernel<<<16 + ROWS/64, 256>>>(x, proj_w, proj_b,
                                               fusion_w, fusion_b,
                                               loc_out_w, loc_out_b,
                                               glb_out_w, glb_out_b);
    qkv_kernel<<<dim3(ROWS/64, 2), 256>>>(loc_in_w, loc_in_b, glb_in_w, glb_in_b);
    attn_kernel<<<1024, 256>>>();
    fused_score_kernel<<<ROWS/64, 256>>>(pool_w1, pool_b1, pool_w2, pool_b2);
    pool_out_kernel<<<BATCH, 256>>>(out);
}